// round 2
// baseline (speedup 1.0000x reference)
#include <cuda.h>
#include <cuda_runtime.h>
#include <cuda_fp16.h>
#include <cstdint>

// ============================================================================
// out = elu( (adj>0 ? (input@W)/cnt_row : 0) ), cnt_row = #(adj>0 in row);
// cnt==0 rows: softmax over all-(-9e15) row is uniform 1/256.
// (the 'a' vector and leaky_relu provably cancel: scores are row-constant,
//  softmax is shift-invariant -> exactly uniform over the adj mask)
//
// sm_103 PTX target (no 'a' features!): mma.sync fp16 + cp.async pipeline.
// ============================================================================

#define N_ROWS 200000
#define K_DIM  512
#define M_DIM  256
#define BM     128
#define BK     32
#define STAGES 4
#define NITER  (K_DIM / BK)     // 16
#define THREADS 256             // 8 warps: 2 (m) x 4 (n), warp tile 64x64

// --- shared memory layout (bytes) -------------------------------------------
// A: fp32 [128][32+4pad]  rows of 144 B        -> conflict-free LDS.64 frags
// B: fp16 [256][32+8pad]  rows of 80 B         -> conflict-free LDS.32 frags
#define A_STAGE_B  (BM * 144)              // 18432
#define B_STAGE_B  (M_DIM * 80)            // 20480
#define A_OFF(s)   ((s) * A_STAGE_B)
#define B_BASE     (STAGES * A_STAGE_B)    // 73728
#define B_OFF(s)   (B_BASE + (s) * B_STAGE_B)
#define MASK_BASE  (B_BASE + STAGES * B_STAGE_B)   // 155648: u32[128][8]
#define CNT_BASE   (MASK_BASE + 128 * 8 * 4)       // +4096:  int[128][2]
#define SMEM_TOTAL (CNT_BASE + 128 * 2 * 4)        // 160768

// --- device scratch: W transposed to [M][K], fp16 RN -------------------------
__device__ __half g_Wh[M_DIM * K_DIM];

// ============================================================================
// helpers (sm_80-level PTX only)
// ============================================================================
__device__ __forceinline__ uint32_t smem_u32(const void* p) {
    uint32_t a;
    asm("{ .reg .u64 t; cvta.to.shared.u64 t, %1; cvt.u32.u64 %0, t; }"
        : "=r"(a) : "l"(p));
    return a;
}
__device__ __forceinline__ uint64_t to_global(const void* p) {
    uint64_t g;
    asm("cvta.to.global.u64 %0, %1;" : "=l"(g) : "l"(p));
    return g;
}
__device__ __forceinline__ void cp16(uint32_t dst, uint64_t src) {
    asm volatile("cp.async.cg.shared.global [%0], [%1], 16;"
                 :: "r"(dst), "l"(src) : "memory");
}
__device__ __forceinline__ void cp_commit() {
    asm volatile("cp.async.commit_group;" ::: "memory");
}
template <int N>
__device__ __forceinline__ void cp_wait() {
    asm volatile("cp.async.wait_group %0;" :: "n"(N) : "memory");
}
__device__ __forceinline__ float2 lds64f(uint32_t a) {
    float2 v;
    asm volatile("ld.shared.v2.f32 {%0,%1}, [%2];" : "=f"(v.x), "=f"(v.y) : "r"(a));
    return v;
}
__device__ __forceinline__ uint32_t lds32(uint32_t a) {
    uint32_t v;
    asm volatile("ld.shared.b32 %0, [%1];" : "=r"(v) : "r"(a));
    return v;
}
// pack two fp32 -> fp16x2 with round-to-nearest (lo = first arg)
__device__ __forceinline__ uint32_t packh2(float lo, float hi) {
    uint32_t d;
    asm("cvt.rn.f16x2.f32 %0, %1, %2;" : "=r"(d) : "f"(hi), "f"(lo));
    return d;
}
__device__ __forceinline__ void mma16816(float* c, const uint32_t* a,
                                         const uint32_t* b) {
    asm volatile(
        "mma.sync.aligned.m16n8k16.row.col.f32.f16.f16.f32 "
        "{%0,%1,%2,%3}, {%4,%5,%6,%7}, {%8,%9}, {%0,%1,%2,%3};"
        : "+f"(c[0]), "+f"(c[1]), "+f"(c[2]), "+f"(c[3])
        : "r"(a[0]), "r"(a[1]), "r"(a[2]), "r"(a[3]), "r"(b[0]), "r"(b[1]));
}

// ============================================================================
// prep: W [K=512, M=256] row-major fp32 -> g_Wh [M][K] fp16 (RN)
// ============================================================================
__global__ void prep_wh_kernel(const float* __restrict__ W) {
    int idx = blockIdx.x * blockDim.x + threadIdx.x;   // 0..131071
    int k = idx >> 8;          // 0..511
    int m = idx & 255;         // 0..255
    g_Wh[m * K_DIM + k] = __float2half_rn(W[idx]);
}

// ============================================================================
// producer: cp.async one K-stage of A (fp32) and B (fp16) into ring slot
// ============================================================================
__device__ __forceinline__ void produce_stage(uint32_t sb, const float* inp,
                                              int tile, int p, int tid) {
    const int s = p & (STAGES - 1);
    // A: 128 rows x 32 fp32 = 128 B/row; 2 threads per row, 64 B each
    {
        int r = tid >> 1;
        int gr = tile + r;
        if (gr > N_ROWS - 1) gr = N_ROWS - 1;
        uint64_t src = to_global(inp + (size_t)gr * K_DIM + p * BK) +
                       (uint64_t)((tid & 1) * 64);
        uint32_t dst = sb + A_OFF(s) + r * 144 + (tid & 1) * 64;
        #pragma unroll
        for (int j = 0; j < 4; j++) cp16(dst + j * 16, src + j * 16);
    }
    // B: 256 rows x 32 fp16 = 64 B/row; 1 thread per row
    {
        uint64_t src = to_global(g_Wh + (size_t)tid * K_DIM + p * BK);
        uint32_t dst = sb + B_OFF(s) + tid * 80;
        #pragma unroll
        for (int j = 0; j < 4; j++) cp16(dst + j * 16, src + j * 16);
    }
    cp_commit();
}

// ============================================================================
// fused GEMM (mma.sync fp16) + adj mask/count + uniform attention + elu
// ============================================================================
__global__ void __launch_bounds__(THREADS, 1) gat_kernel(
    const float* __restrict__ inp,
    const int* __restrict__ adj,
    float* __restrict__ out)
{
    extern __shared__ char smem[];
    const uint32_t sb = smem_u32(smem);
    uint32_t* smask = (uint32_t*)(smem + MASK_BASE);   // [128][8]
    int* scnt = (int*)(smem + CNT_BASE);               // [128][2]

    const int tid  = threadIdx.x;
    const int lane = tid & 31;
    const int wid  = tid >> 5;
    const int wm   = wid >> 2;   // 0..1 : 64-row band
    const int wn   = wid & 3;    // 0..3 : 64-col band
    const int tile = blockIdx.x * BM;

    // ---- prologue: prefetch first STAGES-1 K-chunks -------------------------
    #pragma unroll
    for (int p = 0; p < STAGES - 1; p++) produce_stage(sb, inp, tile, p, tid);

    // ---- adj mask + count pass (overlaps the cp.async prologue) -------------
    {
        int r = tid >> 1;            // row within tile
        int h = tid & 1;             // which 128-col half
        int gr = tile + r;
        if (gr > N_ROWS - 1) gr = N_ROWS - 1;
        const int4* ap = (const int4*)(adj + (size_t)gr * M_DIM + h * 128);
        int cnt = 0;
        #pragma unroll
        for (int g = 0; g < 4; g++) {
            uint32_t m = 0;
            #pragma unroll
            for (int q = 0; q < 8; q++) {
                int4 v = __ldg(ap + g * 8 + q);
                m |= (v.x > 0 ? 1u : 0u) << (q * 4 + 0);
                m |= (v.y > 0 ? 1u : 0u) << (q * 4 + 1);
                m |= (v.z > 0 ? 1u : 0u) << (q * 4 + 2);
                m |= (v.w > 0 ? 1u : 0u) << (q * 4 + 3);
            }
            smask[r * 8 + h * 4 + g] = m;
            cnt += __popc(m);
        }
        scnt[r * 2 + h] = cnt;
    }

    // ---- mainloop ------------------------------------------------------------
    float c[4][8][4];
    #pragma unroll
    for (int mf = 0; mf < 4; mf++)
        #pragma unroll
        for (int nf = 0; nf < 8; nf++)
            #pragma unroll
            for (int e = 0; e < 4; e++) c[mf][nf][e] = 0.0f;

    const int arow = lane >> 2;          // 0..7
    const int acol = (lane & 3) * 2;     // 0,2,4,6

    #pragma unroll 1
    for (int i = 0; i < NITER; i++) {
        const int s = i & (STAGES - 1);
        // exact tail-aware wait: remaining pending groups after this wait
        if (i < NITER - (STAGES - 2))      cp_wait<STAGES - 2>();
        else if (i == NITER - 2)           cp_wait<1>();
        else                               cp_wait<0>();
        __syncthreads();

        if (i + STAGES - 1 < NITER)
            produce_stage(sb, inp, tile, i + STAGES - 1, tid);

        const uint32_t aB = sb + A_OFF(s) + (wm * 64) * 144;
        const uint32_t bB = sb + B_OFF(s) + (wn * 64) * 80;

        #pragma unroll
        for (int ks = 0; ks < 2; ks++) {
            const int kk = ks * 16 + acol;   // 0..31
            uint32_t ra[4][4];
            #pragma unroll
            for (int mf = 0; mf < 4; mf++) {
                uint32_t rb0 = aB + (mf * 16 + arow) * 144;
                uint32_t rb1 = rb0 + 8 * 144;
                float2 x0 = lds64f(rb0 + kk * 4);
                float2 x1 = lds64f(rb1 + kk * 4);
                float2 x2 = lds64f(rb0 + (kk + 8) * 4);
                float2 x3 = lds64f(rb1 + (kk + 8) * 4);
                ra[mf][0] = packh2(x0.x, x0.y);
                ra[mf][1] = packh2(x1.x, x1.y);
                ra[mf][2] = packh2(x2.x, x2.y);
                ra[mf][3] = packh2(x3.x, x3.y);
            }
            uint32_t rb[8][2];
            #pragma unroll
            for (int nf = 0; nf < 8; nf++) {
                uint32_t nb = bB + (nf * 8 + arow) * 80;
                rb[nf][0] = lds32(nb + kk * 2);
                rb[nf][1] = lds32(nb + (kk + 8) * 2);
            }
            #pragma unroll
            for (int mf = 0; mf < 4; mf++)
                #pragma unroll
                for (int nf = 0; nf < 8; nf++)
                    mma16816(c[mf][nf], ra[mf], rb[nf]);
        }
    }

    // ---- epilogue: scale by 1/cnt on mask, elu, store ------------------------
    #pragma unroll
    for (int mf = 0; mf < 4; mf++) {
        const int r0 = wm * 64 + mf * 16 + arow;
        #pragma unroll
        for (int half = 0; half < 2; half++) {
            const int rr = r0 + half * 8;
            const int grow = tile + rr;
            const bool valid = (grow < N_ROWS);
            const int cnt = scnt[rr * 2] + scnt[rr * 2 + 1];
            const bool all_on = (cnt == 0);
            const float scale = all_on ? (1.0f / 256.0f) : (1.0f / (float)cnt);
            #pragma unroll
            for (int nf = 0; nf < 8; nf++) {
                const int col = wn * 64 + nf * 8 + acol;
                const uint32_t mw = smask[rr * 8 + (col >> 5)];
                float2 o;
                #pragma unroll
                for (int e = 0; e < 2; e++) {
                    float h = c[mf][nf][half * 2 + e];
                    bool on = all_on | (((mw >> ((col + e) & 31)) & 1u) != 0u);
                    float v = on ? h * scale : 0.0f;
                    float res = (v > 0.0f) ? v : (__expf(v) - 1.0f);
                    ((float*)&o)[e] = res;
                }
                if (valid)
                    *(float2*)(out + (size_t)grow * M_DIM + col) = o;
            }
        }
    }
}

// ============================================================================
// host launch
// ============================================================================
extern "C" void kernel_launch(void* const* d_in, const int* in_sizes, int n_in,
                              void* d_out, int out_size) {
    const float* inp = (const float*)d_in[0];
    const int*   adj = (const int*)d_in[1];
    const float* W   = (const float*)d_in[2];
    // d_in[3] ('a') provably cancels in the softmax; unused.
    float* out = (float*)d_out;

    prep_wh_kernel<<<(K_DIM * M_DIM) / 256, 256>>>(W);

    static bool attr_set = false;
    if (!attr_set) {
        cudaFuncSetAttribute(gat_kernel,
                             cudaFuncAttributeMaxDynamicSharedMemorySize,
                             SMEM_TOTAL);
        attr_set = true;
    }
    const int grid = (N_ROWS + BM - 1) / BM;   // 1563
    gat_kernel<<<grid, THREADS, SMEM_TOTAL>>>(inp, adj, out);
}

// round 3
// speedup vs baseline: 1.0464x; 1.0464x over previous
#include <cuda.h>
#include <cuda_runtime.h>
#include <cuda_fp16.h>
#include <cstdint>

// ============================================================================
// out = elu( (adj>0 ? (input@W)/cnt_row : 0) ), cnt_row = #(adj>0 in row);
// cnt==0 rows: softmax over all-(-9e15) row is uniform 1/256.
// sm_103 PTX target (no 'a' features): mma.sync fp16 + cp.async pipeline.
// R3: 512 threads (4x4 warp grid, 32x64 warp tiles) to double occupancy —
//     R2 was latency-bound (occ 12.4%, nothing saturated, DRAM already at
//     minimum traffic).
// ============================================================================

#define N_ROWS 200000
#define K_DIM  512
#define M_DIM  256
#define BM     128
#define BK     32
#define STAGES 4
#define NITER  (K_DIM / BK)     // 16
#define THREADS 512             // 16 warps: 4 (m) x 4 (n), warp tile 32x64

// --- shared memory layout (bytes) -------------------------------------------
#define A_STAGE_B  (BM * 144)              // fp32 [128][32+4pad]
#define B_STAGE_B  (M_DIM * 80)            // fp16 [256][32+8pad]
#define A_OFF(s)   ((s) * A_STAGE_B)
#define B_BASE     (STAGES * A_STAGE_B)    // 73728
#define B_OFF(s)   (B_BASE + (s) * B_STAGE_B)
#define MASK_BASE  (B_BASE + STAGES * B_STAGE_B)   // 155648: u32[128][8]
#define CNT_BASE   (MASK_BASE + 128 * 8 * 4)       // +4096:  int[128][4]
#define SMEM_TOTAL (CNT_BASE + 128 * 4 * 4)        // 161792

// --- device scratch: W transposed to [M][K], fp16 RN -------------------------
__device__ __half g_Wh[M_DIM * K_DIM];

// ============================================================================
// helpers (sm_80-level PTX only)
// ============================================================================
__device__ __forceinline__ uint32_t smem_u32(const void* p) {
    uint32_t a;
    asm("{ .reg .u64 t; cvta.to.shared.u64 t, %1; cvt.u32.u64 %0, t; }"
        : "=r"(a) : "l"(p));
    return a;
}
__device__ __forceinline__ uint64_t to_global(const void* p) {
    uint64_t g;
    asm("cvta.to.global.u64 %0, %1;" : "=l"(g) : "l"(p));
    return g;
}
__device__ __forceinline__ void cp16(uint32_t dst, uint64_t src) {
    asm volatile("cp.async.cg.shared.global [%0], [%1], 16;"
                 :: "r"(dst), "l"(src) : "memory");
}
__device__ __forceinline__ void cp_commit() {
    asm volatile("cp.async.commit_group;" ::: "memory");
}
template <int N>
__device__ __forceinline__ void cp_wait() {
    asm volatile("cp.async.wait_group %0;" :: "n"(N) : "memory");
}
__device__ __forceinline__ float2 lds64f(uint32_t a) {
    float2 v;
    asm volatile("ld.shared.v2.f32 {%0,%1}, [%2];" : "=f"(v.x), "=f"(v.y) : "r"(a));
    return v;
}
__device__ __forceinline__ uint32_t lds32(uint32_t a) {
    uint32_t v;
    asm volatile("ld.shared.b32 %0, [%1];" : "=r"(v) : "r"(a));
    return v;
}
__device__ __forceinline__ uint32_t packh2(float lo, float hi) {
    uint32_t d;
    asm("cvt.rn.f16x2.f32 %0, %1, %2;" : "=r"(d) : "f"(hi), "f"(lo));
    return d;
}
__device__ __forceinline__ void mma16816(float* c, const uint32_t* a,
                                         const uint32_t* b) {
    asm volatile(
        "mma.sync.aligned.m16n8k16.row.col.f32.f16.f16.f32 "
        "{%0,%1,%2,%3}, {%4,%5,%6,%7}, {%8,%9}, {%0,%1,%2,%3};"
        : "+f"(c[0]), "+f"(c[1]), "+f"(c[2]), "+f"(c[3])
        : "r"(a[0]), "r"(a[1]), "r"(a[2]), "r"(a[3]), "r"(b[0]), "r"(b[1]));
}

// ============================================================================
// prep: W [K=512, M=256] row-major fp32 -> g_Wh [M][K] fp16 (RN)
// ============================================================================
__global__ void prep_wh_kernel(const float* __restrict__ W) {
    int idx = blockIdx.x * blockDim.x + threadIdx.x;   // 0..131071
    int k = idx >> 8;
    int m = idx & 255;
    g_Wh[m * K_DIM + k] = __float2half_rn(W[idx]);
}

// ============================================================================
// producer: cp.async one K-stage of A (fp32) and B (fp16), 512 threads
// ============================================================================
__device__ __forceinline__ void produce_stage(uint32_t sb, const float* inp,
                                              int tile, int p, int tid) {
    const int s = p & (STAGES - 1);
    // A: 128 rows x 128 B; 4 threads/row, 32 B each
    {
        int r = tid >> 2;
        int seg = tid & 3;
        int gr = tile + r;
        if (gr > N_ROWS - 1) gr = N_ROWS - 1;
        uint64_t src = to_global(inp + (size_t)gr * K_DIM + p * BK) +
                       (uint64_t)(seg * 32);
        uint32_t dst = sb + A_OFF(s) + r * 144 + seg * 32;
        cp16(dst, src);
        cp16(dst + 16, src + 16);
    }
    // B: 256 rows x 64 B; 2 threads/row, 32 B each
    {
        int r = tid >> 1;
        int seg = tid & 1;
        uint64_t src = to_global(g_Wh + (size_t)r * K_DIM + p * BK) +
                       (uint64_t)(seg * 32);
        uint32_t dst = sb + B_OFF(s) + r * 80 + seg * 32;
        cp16(dst, src);
        cp16(dst + 16, src + 16);
    }
    cp_commit();
}

// ============================================================================
// fused GEMM (mma.sync fp16) + adj mask/count + uniform attention + elu
// ============================================================================
__global__ void __launch_bounds__(THREADS, 1) gat_kernel(
    const float* __restrict__ inp,
    const int* __restrict__ adj,
    float* __restrict__ out)
{
    extern __shared__ char smem[];
    const uint32_t sb = smem_u32(smem);
    uint32_t* smask = (uint32_t*)(smem + MASK_BASE);   // [128][8]
    int* scnt = (int*)(smem + CNT_BASE);               // [128][4]

    const int tid  = threadIdx.x;
    const int lane = tid & 31;
    const int wid  = tid >> 5;
    const int wm   = wid >> 2;   // 0..3 : 32-row band
    const int wn   = wid & 3;    // 0..3 : 64-col band
    const int tile = blockIdx.x * BM;

    // ---- prologue: prefetch first STAGES-1 K-chunks -------------------------
    #pragma unroll
    for (int p = 0; p < STAGES - 1; p++) produce_stage(sb, inp, tile, p, tid);

    // ---- adj mask + count (overlaps cp.async prologue) -----------------------
    {
        int r = tid >> 2;            // row within tile
        int q = tid & 3;             // 64-col quarter
        int gr = tile + r;
        if (gr > N_ROWS - 1) gr = N_ROWS - 1;
        const int4* ap = (const int4*)(adj + (size_t)gr * M_DIM + q * 64);
        int cnt = 0;
        #pragma unroll
        for (int g = 0; g < 2; g++) {
            uint32_t m = 0;
            #pragma unroll
            for (int w = 0; w < 8; w++) {
                int4 v = __ldg(ap + g * 8 + w);
                m |= (v.x > 0 ? 1u : 0u) << (w * 4 + 0);
                m |= (v.y > 0 ? 1u : 0u) << (w * 4 + 1);
                m |= (v.z > 0 ? 1u : 0u) << (w * 4 + 2);
                m |= (v.w > 0 ? 1u : 0u) << (w * 4 + 3);
            }
            smask[r * 8 + q * 2 + g] = m;
            cnt += __popc(m);
        }
        scnt[r * 4 + q] = cnt;
    }

    // ---- mainloop ------------------------------------------------------------
    float c[2][8][4];
    #pragma unroll
    for (int mf = 0; mf < 2; mf++)
        #pragma unroll
        for (int nf = 0; nf < 8; nf++)
            #pragma unroll
            for (int e = 0; e < 4; e++) c[mf][nf][e] = 0.0f;

    const int arow = lane >> 2;          // 0..7
    const int acol = (lane & 3) * 2;     // 0,2,4,6

    #pragma unroll 1
    for (int i = 0; i < NITER; i++) {
        const int s = i & (STAGES - 1);
        if (i < NITER - (STAGES - 2))      cp_wait<STAGES - 2>();
        else if (i == NITER - 2)           cp_wait<1>();
        else                               cp_wait<0>();
        __syncthreads();

        if (i + STAGES - 1 < NITER)
            produce_stage(sb, inp, tile, i + STAGES - 1, tid);

        const uint32_t aB = sb + A_OFF(s) + (wm * 32) * 144;
        const uint32_t bB = sb + B_OFF(s) + (wn * 64) * 80;

        #pragma unroll
        for (int ks = 0; ks < 2; ks++) {
            const int kk = ks * 16 + acol;   // 0..31
            uint32_t ra[2][4];
            #pragma unroll
            for (int mf = 0; mf < 2; mf++) {
                uint32_t rb0 = aB + (mf * 16 + arow) * 144;
                uint32_t rb1 = rb0 + 8 * 144;
                float2 x0 = lds64f(rb0 + kk * 4);
                float2 x1 = lds64f(rb1 + kk * 4);
                float2 x2 = lds64f(rb0 + (kk + 8) * 4);
                float2 x3 = lds64f(rb1 + (kk + 8) * 4);
                ra[mf][0] = packh2(x0.x, x0.y);
                ra[mf][1] = packh2(x1.x, x1.y);
                ra[mf][2] = packh2(x2.x, x2.y);
                ra[mf][3] = packh2(x3.x, x3.y);
            }
            uint32_t rb[8][2];
            #pragma unroll
            for (int nf = 0; nf < 8; nf++) {
                uint32_t nb = bB + (nf * 8 + arow) * 80;
                rb[nf][0] = lds32(nb + kk * 2);
                rb[nf][1] = lds32(nb + (kk + 8) * 2);
            }
            #pragma unroll
            for (int mf = 0; mf < 2; mf++)
                #pragma unroll
                for (int nf = 0; nf < 8; nf++)
                    mma16816(c[mf][nf], ra[mf], rb[nf]);
        }
    }

    // ---- epilogue: scale by 1/cnt on mask, elu, store ------------------------
    #pragma unroll
    for (int mf = 0; mf < 2; mf++) {
        const int r0 = wm * 32 + mf * 16 + arow;
        #pragma unroll
        for (int half = 0; half < 2; half++) {
            const int rr = r0 + half * 8;
            const int grow = tile + rr;
            const bool valid = (grow < N_ROWS);
            const int cnt = scnt[rr * 4] + scnt[rr * 4 + 1] +
                            scnt[rr * 4 + 2] + scnt[rr * 4 + 3];
            const bool all_on = (cnt == 0);
            const float scale = all_on ? (1.0f / 256.0f) : (1.0f / (float)cnt);
            #pragma unroll
            for (int nf = 0; nf < 8; nf++) {
                const int col = wn * 64 + nf * 8 + acol;
                const uint32_t mw = smask[rr * 8 + (col >> 5)];
                float2 o;
                #pragma unroll
                for (int e = 0; e < 2; e++) {
                    float h = c[mf][nf][half * 2 + e];
                    bool on = all_on | (((mw >> ((col + e) & 31)) & 1u) != 0u);
                    float v = on ? h * scale : 0.0f;
                    float res = (v > 0.0f) ? v : (__expf(v) - 1.0f);
                    ((float*)&o)[e] = res;
                }
                if (valid)
                    *(float2*)(out + (size_t)grow * M_DIM + col) = o;
            }
        }
    }
}

// ============================================================================
// host launch
// ============================================================================
extern "C" void kernel_launch(void* const* d_in, const int* in_sizes, int n_in,
                              void* d_out, int out_size) {
    const float* inp = (const float*)d_in[0];
    const int*   adj = (const int*)d_in[1];
    const float* W   = (const float*)d_in[2];
    float* out = (float*)d_out;

    prep_wh_kernel<<<(K_DIM * M_DIM) / 256, 256>>>(W);

    static bool attr_set = false;
    if (!attr_set) {
        cudaFuncSetAttribute(gat_kernel,
                             cudaFuncAttributeMaxDynamicSharedMemorySize,
                             SMEM_TOTAL);
        attr_set = true;
    }
    const int grid = (N_ROWS + BM - 1) / BM;   // 1563
    gat_kernel<<<grid, THREADS, SMEM_TOTAL>>>(inp, adj, out);
}

// round 5
// speedup vs baseline: 1.2221x; 1.1679x over previous
#include <cuda.h>
#include <cuda_runtime.h>
#include <cuda_fp16.h>
#include <cstdint>

// ============================================================================
// out = elu( (adj>0 ? (input@W)/cnt_row : 0) ), cnt_row = #(adj>0 in row);
// cnt==0 rows: softmax of all-(-9e15) is uniform 1/256.
// R5: R4's design (TMA staging, smem fp32->fp16 convert, mma.sync) was right;
//     it failed on an smem OVERLAP: CNT [4224,6272) vs A16 [5120,...) — the
//     convert clobbered neighbor counts for rows 56-127 of every tile
//     (~56% of rows wrong == rel_err 0.75). Fixed the layout only.
// ============================================================================

#define N_ROWS 200000
#define K_DIM  512
#define M_DIM  256
#define BM     128
#define BK     64
#define NITER  (K_DIM / BK)     // 8
#define NSTAGE 3
#define THREADS 512             // 16 warps: 4 (m) x 4 (n), warp tile 32x64

// --- shared memory layout (bytes) -------------------------------------------
// MBAR[3] @0, MASK @128 (u32[128][8], ends 4224), CNT @4224 (int[128][4],
// ends 6272), A16 @6272 (16KB fp16 [128][64], ends 22656),
// stages @23552 (1024-aligned, 64KB each):
//   stage s: A32 two 16KB subtiles (fp32 [128][32] SW128) + B 32KB
//   (fp16 [256][64] rows 128B SW128).
#define MBAR(s)    ((s) * 8)
#define MASK_OFF   128
#define CNT_OFF    (MASK_OFF + 128 * 8 * 4)     // 4224
#define A16_OFF    (CNT_OFF + 128 * 4 * 4)      // 6272  (16B aligned)
#define STAGE(s)   (23552 + (s) * 65536)        // 1024-aligned
#define STAGE_B(s) (STAGE(s) + 32768)
#define SMEM_TOTAL (23552 + NSTAGE * 65536)     // 220160
#define TX_BYTES   65536

// --- device scratch: W transposed to [M][K], fp16 RN -------------------------
__device__ __half g_Wh[M_DIM * K_DIM];

// ============================================================================
// helpers (plain sm_90-level PTX; no 'a' features)
// ============================================================================
__device__ __forceinline__ uint32_t smem_u32(const void* p) {
    uint32_t a;
    asm("{ .reg .u64 t; cvta.to.shared.u64 t, %1; cvt.u32.u64 %0, t; }"
        : "=r"(a) : "l"(p));
    return a;
}
#define MBARRIER_INIT(mbar, count) \
    asm volatile("mbarrier.init.shared.b64 [%0], %1;" \
        :: "r"((uint32_t)(mbar)), "r"((uint32_t)(count)) : "memory")
#define MBARRIER_EXPECT_TX(mbar, bytes) \
    asm volatile("mbarrier.arrive.expect_tx.shared.b64 _, [%0], %1;" \
        :: "r"((uint32_t)(mbar)), "r"((uint32_t)(bytes)) : "memory")
#define MBARRIER_WAIT_PARITY(mbar, parity) do { \
    uint32_t _mbar = (uint32_t)(mbar); \
    uint32_t _par = (uint32_t)(parity); \
    uint32_t _done; \
    asm volatile( \
        "{\n\t.reg .pred p;\n\t" \
        "mbarrier.try_wait.parity.acquire.cta.shared::cta.b64 p, [%1], %2;\n\t" \
        "selp.b32 %0, 1, 0, p;\n\t}" \
        : "=r"(_done) : "r"(_mbar), "r"(_par) : "memory"); \
    if (!_done) { \
        asm volatile( \
            "{\n\t.reg .pred P1;\n\t" \
            "WAIT_LOOP_%=:\n\t" \
            "mbarrier.try_wait.parity.acquire.cta.shared::cta.b64 P1, [%0], %1, 0x989680;\n\t" \
            "@P1 bra.uni WAIT_DONE_%=;\n\t" \
            "bra.uni WAIT_LOOP_%=;\n\t" \
            "WAIT_DONE_%=:\n\t}" \
            :: "r"(_mbar), "r"(_par) : "memory"); \
    } \
} while (0)
#define TMA_LOAD_2D(smem_addr, map_ptr, cx, cy, mbar) \
    asm volatile( \
        "cp.async.bulk.tensor.2d.shared::cta.global.tile.mbarrier::complete_tx::bytes " \
        "[%0], [%1, {%2, %3}], [%4];" \
        :: "r"((uint32_t)(smem_addr)), "l"(map_ptr), \
           "r"((int32_t)(cx)), "r"((int32_t)(cy)), "r"((uint32_t)(mbar)) \
        : "memory")

__device__ __forceinline__ uint32_t lds32(uint32_t a) {
    uint32_t v;
    asm volatile("ld.shared.b32 %0, [%1];" : "=r"(v) : "r"(a));
    return v;
}
__device__ __forceinline__ float4 lds128f(uint32_t a) {
    float4 v;
    asm volatile("ld.shared.v4.f32 {%0,%1,%2,%3}, [%4];"
                 : "=f"(v.x), "=f"(v.y), "=f"(v.z), "=f"(v.w) : "r"(a));
    return v;
}
__device__ __forceinline__ void sts128(uint32_t a, uint32_t r0, uint32_t r1,
                                       uint32_t r2, uint32_t r3) {
    asm volatile("st.shared.v4.b32 [%0], {%1,%2,%3,%4};"
                 :: "r"(a), "r"(r0), "r"(r1), "r"(r2), "r"(r3) : "memory");
}
__device__ __forceinline__ uint32_t packh2(float lo, float hi) {
    uint32_t d;
    asm("cvt.rn.f16x2.f32 %0, %1, %2;" : "=r"(d) : "f"(hi), "f"(lo));
    return d;
}
__device__ __forceinline__ void mma16816(float* c, const uint32_t* a,
                                         const uint32_t* b) {
    asm volatile(
        "mma.sync.aligned.m16n8k16.row.col.f32.f16.f16.f32 "
        "{%0,%1,%2,%3}, {%4,%5,%6,%7}, {%8,%9}, {%0,%1,%2,%3};"
        : "+f"(c[0]), "+f"(c[1]), "+f"(c[2]), "+f"(c[3])
        : "r"(a[0]), "r"(a[1]), "r"(a[2]), "r"(a[3]), "r"(b[0]), "r"(b[1]));
}

// ============================================================================
// prep: W [K=512, M=256] row-major fp32 -> g_Wh [M][K] fp16 (RN)
// ============================================================================
__global__ void prep_wh_kernel(const float* __restrict__ W) {
    int idx = blockIdx.x * blockDim.x + threadIdx.x;
    int k = idx >> 8;
    int m = idx & 255;
    g_Wh[m * K_DIM + k] = __float2half_rn(W[idx]);
}

// ============================================================================
// fused GEMM (TMA + smem-convert + mma.sync fp16) + uniform attention + elu
// ============================================================================
__global__ void __launch_bounds__(THREADS, 1) gat_kernel(
    const __grid_constant__ CUtensorMap tmap_a,
    const __grid_constant__ CUtensorMap tmap_b,
    const int* __restrict__ adj,
    float* __restrict__ out)
{
    extern __shared__ char smem[];
    const uint32_t sb = smem_u32(smem);
    uint32_t* smask = (uint32_t*)(smem + MASK_OFF);   // [128][8]
    int* scnt = (int*)(smem + CNT_OFF);               // [128][4]

    const int tid  = threadIdx.x;
    const int lane = tid & 31;
    const int wid  = tid >> 5;
    const int wm   = wid >> 2;   // 0..3 : 32-row band
    const int wn   = wid & 3;    // 0..3 : 64-col band
    const int tile = blockIdx.x * BM;

    // ---- mbarrier init + TMA prologue ----------------------------------------
    if (tid == 0) {
        MBARRIER_INIT(sb + MBAR(0), 1);
        MBARRIER_INIT(sb + MBAR(1), 1);
        MBARRIER_INIT(sb + MBAR(2), 1);
    }
    __syncthreads();
    if (tid == 0) {
        #pragma unroll
        for (int j = 0; j < NSTAGE; j++) {
            MBARRIER_EXPECT_TX(sb + MBAR(j), TX_BYTES);
            TMA_LOAD_2D(sb + STAGE(j),         &tmap_a, j * BK,      tile, sb + MBAR(j));
            TMA_LOAD_2D(sb + STAGE(j) + 16384, &tmap_a, j * BK + 32, tile, sb + MBAR(j));
            TMA_LOAD_2D(sb + STAGE_B(j),       &tmap_b, j * BK,      0,    sb + MBAR(j));
        }
    }

    // ---- adj mask + count (overlaps TMA flight) -------------------------------
    {
        int r = tid >> 2;
        int q = tid & 3;
        int gr = tile + r;
        if (gr > N_ROWS - 1) gr = N_ROWS - 1;
        const int4* ap = (const int4*)(adj + (size_t)gr * M_DIM + q * 64);
        int cnt = 0;
        #pragma unroll
        for (int g = 0; g < 2; g++) {
            uint32_t m = 0;
            #pragma unroll
            for (int w = 0; w < 8; w++) {
                int4 v = __ldg(ap + g * 8 + w);
                m |= (v.x > 0 ? 1u : 0u) << (w * 4 + 0);
                m |= (v.y > 0 ? 1u : 0u) << (w * 4 + 1);
                m |= (v.z > 0 ? 1u : 0u) << (w * 4 + 2);
                m |= (v.w > 0 ? 1u : 0u) << (w * 4 + 3);
            }
            smask[r * 8 + q * 2 + g] = m;
            cnt += __popc(m);
        }
        scnt[r * 4 + q] = cnt;
    }

    // ---- per-thread constants --------------------------------------------------
    const int arow = lane >> 2;                 // 0..7
    const uint32_t acolb = (lane & 3) * 4;      // byte-in-unit for frags
    const uint32_t xorf  = (uint32_t)arow << 4; // SW128 XOR field (row&7)

    // convert-phase mapping: r = tid&127 (row), q = tid>>7 (k-quarter of 16)
    const int cr = tid & 127;
    const int cq = tid >> 7;                    // 0..3
    const uint32_t crx = (uint32_t)(cr & 7) << 4;
    const uint32_t csrc_off = (uint32_t)(cq >> 1) * 16384 + (uint32_t)cr * 128;
    const uint32_t cu0 = (uint32_t)(cq & 1) * 4;
    const uint32_t cdst = sb + A16_OFF + (uint32_t)cr * 128;

    float c[2][8][4];
    #pragma unroll
    for (int mf = 0; mf < 2; mf++)
        #pragma unroll
        for (int nf = 0; nf < 8; nf++)
            #pragma unroll
            for (int e = 0; e < 4; e++) c[mf][nf][e] = 0.0f;

    const uint32_t aR = sb + A16_OFF + (uint32_t)(wm * 32 + arow) * 128;

    // ---- mainloop: 8 x BK=64 ---------------------------------------------------
    #pragma unroll
    for (int i = 0; i < NITER; i++) {
        const int s = i % 3;
        const uint32_t p = (uint32_t)((i / 3) & 1);
        MBARRIER_WAIT_PARITY(sb + MBAR(s), p);

        // convert A32[s] -> A16 (fp16, SW128-XOR layout), conflict-free
        {
            const uint32_t src = sb + STAGE(s) + csrc_off;
            float4 f0 = lds128f(src + (((cu0 + 0) << 4) ^ crx));
            float4 f1 = lds128f(src + (((cu0 + 1) << 4) ^ crx));
            float4 f2 = lds128f(src + (((cu0 + 2) << 4) ^ crx));
            float4 f3 = lds128f(src + (((cu0 + 3) << 4) ^ crx));
            uint32_t h0 = packh2(f0.x, f0.y), h1 = packh2(f0.z, f0.w);
            uint32_t h2 = packh2(f1.x, f1.y), h3 = packh2(f1.z, f1.w);
            uint32_t h4 = packh2(f2.x, f2.y), h5 = packh2(f2.z, f2.w);
            uint32_t h6 = packh2(f3.x, f3.y), h7 = packh2(f3.z, f3.w);
            sts128(cdst + (((uint32_t)(cq * 2 + 0) << 4) ^ crx), h0, h1, h2, h3);
            sts128(cdst + (((uint32_t)(cq * 2 + 1) << 4) ^ crx), h4, h5, h6, h7);
        }
        __syncthreads();

        // fragment loads + MMA
        {
            const uint32_t bR = sb + STAGE_B(s) + (uint32_t)(wn * 64 + arow) * 128;
            #pragma unroll
            for (int ks = 0; ks < 4; ks++) {
                const uint32_t kb = (uint32_t)ks * 32 + acolb;
                const uint32_t o0 = kb ^ xorf;
                const uint32_t o1 = (kb + 16) ^ xorf;
                uint32_t ra[2][4];
                #pragma unroll
                for (int mf = 0; mf < 2; mf++) {
                    const uint32_t rb_ = aR + (uint32_t)mf * 2048;
                    ra[mf][0] = lds32(rb_ + o0);
                    ra[mf][1] = lds32(rb_ + 1024 + o0);
                    ra[mf][2] = lds32(rb_ + o1);
                    ra[mf][3] = lds32(rb_ + 1024 + o1);
                }
                #pragma unroll
                for (int nf = 0; nf < 8; nf++) {
                    const uint32_t nb = bR + (uint32_t)nf * 1024;
                    uint32_t bb[2];
                    bb[0] = lds32(nb + o0);
                    bb[1] = lds32(nb + o1);
                    mma16816(c[0][nf], ra[0], bb);
                    mma16816(c[1][nf], ra[1], bb);
                }
            }
        }
        __syncthreads();

        // refill stage s for iteration i+3
        if (i + NSTAGE < NITER && tid == 0) {
            MBARRIER_EXPECT_TX(sb + MBAR(s), TX_BYTES);
            TMA_LOAD_2D(sb + STAGE(s),         &tmap_a, (i + 3) * BK,      tile, sb + MBAR(s));
            TMA_LOAD_2D(sb + STAGE(s) + 16384, &tmap_a, (i + 3) * BK + 32, tile, sb + MBAR(s));
            TMA_LOAD_2D(sb + STAGE_B(s),       &tmap_b, (i + 3) * BK,      0,    sb + MBAR(s));
        }
    }

    // ---- epilogue: scale by 1/cnt on mask, elu, store ---------------------------
    #pragma unroll
    for (int mf = 0; mf < 2; mf++) {
        const int r0 = wm * 32 + mf * 16 + arow;
        #pragma unroll
        for (int half = 0; half < 2; half++) {
            const int rr = r0 + half * 8;
            const int grow = tile + rr;
            const bool valid = (grow < N_ROWS);
            const int cnt = scnt[rr * 4] + scnt[rr * 4 + 1] +
                            scnt[rr * 4 + 2] + scnt[rr * 4 + 3];
            const bool all_on = (cnt == 0);
            const float scale = all_on ? (1.0f / 256.0f) : (1.0f / (float)cnt);
            #pragma unroll
            for (int nf = 0; nf < 8; nf++) {
                const int col = wn * 64 + nf * 8 + (int)(lane & 3) * 2;
                const uint32_t mw = smask[rr * 8 + (col >> 5)];
                float2 o;
                #pragma unroll
                for (int e = 0; e < 2; e++) {
                    float h = c[mf][nf][half * 2 + e];
                    bool on = all_on | (((mw >> ((col + e) & 31)) & 1u) != 0u);
                    float v = on ? h * scale : 0.0f;
                    float res = (v > 0.0f) ? v : (__expf(v) - 1.0f);
                    ((float*)&o)[e] = res;
                }
                if (valid)
                    *(float2*)(out + (size_t)grow * M_DIM + col) = o;
            }
        }
    }
}

// ============================================================================
// host launch
// ============================================================================
typedef CUresult (*EncodeTiledFn)(
    CUtensorMap*, CUtensorMapDataType, cuuint32_t, void*,
    const cuuint64_t*, const cuuint64_t*, const cuuint32_t*, const cuuint32_t*,
    CUtensorMapInterleave, CUtensorMapSwizzle, CUtensorMapL2promotion,
    CUtensorMapFloatOOBfill);

extern "C" void kernel_launch(void* const* d_in, const int* in_sizes, int n_in,
                              void* d_out, int out_size) {
    const float* inp = (const float*)d_in[0];
    const int*   adj = (const int*)d_in[1];
    const float* W   = (const float*)d_in[2];
    // d_in[3] ('a') provably cancels in the softmax; unused.
    float* out = (float*)d_out;

    prep_wh_kernel<<<(K_DIM * M_DIM) / 256, 256>>>(W);

    void* wh_ptr = nullptr;
    cudaGetSymbolAddress(&wh_ptr, g_Wh);

    void* fp = nullptr;
    cudaDriverEntryPointQueryResult qres;
    cudaGetDriverEntryPointByVersion("cuTensorMapEncodeTiled", &fp, 12000,
                                     cudaEnableDefault, &qres);
    EncodeTiledFn enc = (EncodeTiledFn)fp;

    alignas(64) CUtensorMap tmA;
    alignas(64) CUtensorMap tmB;
    {
        cuuint64_t dims[2]    = {(cuuint64_t)K_DIM, (cuuint64_t)N_ROWS};
        cuuint64_t strides[1] = {(cuuint64_t)K_DIM * sizeof(float)};
        cuuint32_t box[2]     = {32u, (cuuint32_t)BM};      // 128B x 128 rows
        cuuint32_t es[2]      = {1, 1};
        enc(&tmA, CU_TENSOR_MAP_DATA_TYPE_FLOAT32, 2, (void*)inp,
            dims, strides, box, es,
            CU_TENSOR_MAP_INTERLEAVE_NONE, CU_TENSOR_MAP_SWIZZLE_128B,
            CU_TENSOR_MAP_L2_PROMOTION_L2_128B, CU_TENSOR_MAP_FLOAT_OOB_FILL_NONE);
    }
    {
        cuuint64_t dims[2]    = {(cuuint64_t)K_DIM, (cuuint64_t)M_DIM};
        cuuint64_t strides[1] = {(cuuint64_t)K_DIM * sizeof(__half)};
        cuuint32_t box[2]     = {64u, (cuuint32_t)M_DIM};   // 128B x 256 rows
        cuuint32_t es[2]      = {1, 1};
        enc(&tmB, CU_TENSOR_MAP_DATA_TYPE_FLOAT16, 2, wh_ptr,
            dims, strides, box, es,
            CU_TENSOR_MAP_INTERLEAVE_NONE, CU_TENSOR_MAP_SWIZZLE_128B,
            CU_TENSOR_MAP_L2_PROMOTION_L2_128B, CU_TENSOR_MAP_FLOAT_OOB_FILL_NONE);
    }

    static bool attr_set = false;
    if (!attr_set) {
        cudaFuncSetAttribute(gat_kernel,
                             cudaFuncAttributeMaxDynamicSharedMemorySize,
                             SMEM_TOTAL);
        attr_set = true;
    }
    const int grid = (N_ROWS + BM - 1) / BM;   // 1563
    gat_kernel<<<grid, THREADS, SMEM_TOTAL>>>(tmA, tmB, adj, out);
}

// round 6
// speedup vs baseline: 1.2770x; 1.0450x over previous
#include <cuda.h>
#include <cuda_runtime.h>
#include <cuda_fp16.h>
#include <cstdint>

// ============================================================================
// out = elu( (adj>0 ? (input@W)/cnt_row : 0) ), cnt_row = #(adj>0 in row);
// cnt==0 rows: softmax of all-(-9e15) is uniform 1/256.
// R6: R5 was serialization-bound (issue 20%, 2 syncs/iter, phase ping-pong).
//     Now: A16 double-buffer so convert(i+1) overlaps MMA(i) with ONE sync per
//     iter; A32 3-slot / B 2-slot TMA rings with per-component mbarriers;
//     ldmatrix.x4 fragment loads (4x fewer LDS instructions, conflict-free
//     under the SW128 XOR).
// ============================================================================

#define N_ROWS 200000
#define K_DIM  512
#define M_DIM  256
#define BM     128
#define BK     64
#define NITER  (K_DIM / BK)     // 8
#define THREADS 512             // 16 warps: 4 (m) x 4 (n), warp tile 32x64

// --- shared memory layout (bytes) -------------------------------------------
// mbars: A slots 0..2 @0,8,16 ; B slots 0..1 @24,32
#define MBAR_A(s)  ((s) * 8)
#define MBAR_B(s)  (24 + (s) * 8)
#define MASK_OFF   128                          // u32[128][8]  -> 4224
#define CNT_OFF    (MASK_OFF + 128 * 8 * 4)     // int[128][4]  -> 6272
#define A16_OFF    (CNT_OFF + 128 * 4 * 4)      // 2 x 16KB     -> 39040
#define A32_OFF(s) (39936 + (s) * 32768)        // 3 x 32KB (1024-aligned)
#define B_OFF(s)   (39936 + 98304 + (s) * 32768) // 2 x 32KB
#define SMEM_TOTAL (39936 + 98304 + 65536)      // 203776
#define TXA        32768
#define TXB        32768

// --- device scratch: W transposed to [M][K], fp16 RN -------------------------
__device__ __half g_Wh[M_DIM * K_DIM];

// ============================================================================
// helpers (plain sm_90-level PTX; no 'a' features)
// ============================================================================
__device__ __forceinline__ uint32_t smem_u32(const void* p) {
    uint32_t a;
    asm("{ .reg .u64 t; cvta.to.shared.u64 t, %1; cvt.u32.u64 %0, t; }"
        : "=r"(a) : "l"(p));
    return a;
}
#define MBARRIER_INIT(mbar, count) \
    asm volatile("mbarrier.init.shared.b64 [%0], %1;" \
        :: "r"((uint32_t)(mbar)), "r"((uint32_t)(count)) : "memory")
#define MBARRIER_EXPECT_TX(mbar, bytes) \
    asm volatile("mbarrier.arrive.expect_tx.shared.b64 _, [%0], %1;" \
        :: "r"((uint32_t)(mbar)), "r"((uint32_t)(bytes)) : "memory")
#define MBARRIER_WAIT_PARITY(mbar, parity) do { \
    uint32_t _mbar = (uint32_t)(mbar); \
    uint32_t _par = (uint32_t)(parity); \
    uint32_t _done; \
    asm volatile( \
        "{\n\t.reg .pred p;\n\t" \
        "mbarrier.try_wait.parity.acquire.cta.shared::cta.b64 p, [%1], %2;\n\t" \
        "selp.b32 %0, 1, 0, p;\n\t}" \
        : "=r"(_done) : "r"(_mbar), "r"(_par) : "memory"); \
    if (!_done) { \
        asm volatile( \
            "{\n\t.reg .pred P1;\n\t" \
            "WAIT_LOOP_%=:\n\t" \
            "mbarrier.try_wait.parity.acquire.cta.shared::cta.b64 P1, [%0], %1, 0x989680;\n\t" \
            "@P1 bra.uni WAIT_DONE_%=;\n\t" \
            "bra.uni WAIT_LOOP_%=;\n\t" \
            "WAIT_DONE_%=:\n\t}" \
            :: "r"(_mbar), "r"(_par) : "memory"); \
    } \
} while (0)
#define TMA_LOAD_2D(smem_addr, map_ptr, cx, cy, mbar) \
    asm volatile( \
        "cp.async.bulk.tensor.2d.shared::cta.global.tile.mbarrier::complete_tx::bytes " \
        "[%0], [%1, {%2, %3}], [%4];" \
        :: "r"((uint32_t)(smem_addr)), "l"(map_ptr), \
           "r"((int32_t)(cx)), "r"((int32_t)(cy)), "r"((uint32_t)(mbar)) \
        : "memory")

__device__ __forceinline__ float4 lds128f(uint32_t a) {
    float4 v;
    asm volatile("ld.shared.v4.f32 {%0,%1,%2,%3}, [%4];"
                 : "=f"(v.x), "=f"(v.y), "=f"(v.z), "=f"(v.w) : "r"(a));
    return v;
}
__device__ __forceinline__ void sts128(uint32_t a, uint32_t r0, uint32_t r1,
                                       uint32_t r2, uint32_t r3) {
    asm volatile("st.shared.v4.b32 [%0], {%1,%2,%3,%4};"
                 :: "r"(a), "r"(r0), "r"(r1), "r"(r2), "r"(r3) : "memory");
}
__device__ __forceinline__ void ldsm_x4(uint32_t* r, uint32_t addr) {
    asm volatile("ldmatrix.sync.aligned.m8n8.x4.shared.b16 {%0,%1,%2,%3}, [%4];"
                 : "=r"(r[0]), "=r"(r[1]), "=r"(r[2]), "=r"(r[3]) : "r"(addr));
}
__device__ __forceinline__ uint32_t packh2(float lo, float hi) {
    uint32_t d;
    asm("cvt.rn.f16x2.f32 %0, %1, %2;" : "=r"(d) : "f"(hi), "f"(lo));
    return d;
}
__device__ __forceinline__ void mma16816(float* c, const uint32_t* a,
                                         const uint32_t* b) {
    asm volatile(
        "mma.sync.aligned.m16n8k16.row.col.f32.f16.f16.f32 "
        "{%0,%1,%2,%3}, {%4,%5,%6,%7}, {%8,%9}, {%0,%1,%2,%3};"
        : "+f"(c[0]), "+f"(c[1]), "+f"(c[2]), "+f"(c[3])
        : "r"(a[0]), "r"(a[1]), "r"(a[2]), "r"(a[3]), "r"(b[0]), "r"(b[1]));
}

// ============================================================================
// prep: W [K=512, M=256] row-major fp32 -> g_Wh [M][K] fp16 (RN)
// ============================================================================
__global__ void prep_wh_kernel(const float* __restrict__ W) {
    int idx = blockIdx.x * blockDim.x + threadIdx.x;
    int k = idx >> 8;
    int m = idx & 255;
    g_Wh[m * K_DIM + k] = __float2half_rn(W[idx]);
}

// ============================================================================
// fused GEMM (TMA + overlapped smem-convert + ldmatrix + mma.sync) + attention
// ============================================================================
__global__ void __launch_bounds__(THREADS, 1) gat_kernel(
    const __grid_constant__ CUtensorMap tmap_a,
    const __grid_constant__ CUtensorMap tmap_b,
    const int* __restrict__ adj,
    float* __restrict__ out)
{
    extern __shared__ char smem[];
    const uint32_t sb = smem_u32(smem);
    uint32_t* smask = (uint32_t*)(smem + MASK_OFF);   // [128][8]
    int* scnt = (int*)(smem + CNT_OFF);               // [128][4]

    const int tid  = threadIdx.x;
    const int lane = tid & 31;
    const int wid  = tid >> 5;
    const int wm   = wid >> 2;   // 0..3 : 32-row band
    const int wn   = wid & 3;    // 0..3 : 64-col band
    const int tile = blockIdx.x * BM;

    // ---- mbarrier init + TMA prologue ----------------------------------------
    if (tid == 0) {
        MBARRIER_INIT(sb + MBAR_A(0), 1);
        MBARRIER_INIT(sb + MBAR_A(1), 1);
        MBARRIER_INIT(sb + MBAR_A(2), 1);
        MBARRIER_INIT(sb + MBAR_B(0), 1);
        MBARRIER_INIT(sb + MBAR_B(1), 1);
    }
    __syncthreads();
    if (tid == 0) {
        #pragma unroll
        for (int j = 0; j < 3; j++) {            // A chunks 0..2
            MBARRIER_EXPECT_TX(sb + MBAR_A(j), TXA);
            TMA_LOAD_2D(sb + A32_OFF(j),         &tmap_a, j * BK,      tile, sb + MBAR_A(j));
            TMA_LOAD_2D(sb + A32_OFF(j) + 16384, &tmap_a, j * BK + 32, tile, sb + MBAR_A(j));
        }
        #pragma unroll
        for (int j = 0; j < 2; j++) {            // B chunks 0..1
            MBARRIER_EXPECT_TX(sb + MBAR_B(j), TXB);
            TMA_LOAD_2D(sb + B_OFF(j), &tmap_b, j * BK, 0, sb + MBAR_B(j));
        }
    }

    // ---- adj mask + count (overlaps TMA flight) -------------------------------
    {
        int r = tid >> 2;
        int q = tid & 3;
        int gr = tile + r;
        if (gr > N_ROWS - 1) gr = N_ROWS - 1;
        const int4* ap = (const int4*)(adj + (size_t)gr * M_DIM + q * 64);
        int cnt = 0;
        #pragma unroll
        for (int g = 0; g < 2; g++) {
            uint32_t m = 0;
            #pragma unroll
            for (int w = 0; w < 8; w++) {
                int4 v = __ldg(ap + g * 8 + w);
                m |= (v.x > 0 ? 1u : 0u) << (w * 4 + 0);
                m |= (v.y > 0 ? 1u : 0u) << (w * 4 + 1);
                m |= (v.z > 0 ? 1u : 0u) << (w * 4 + 2);
                m |= (v.w > 0 ? 1u : 0u) << (w * 4 + 3);
            }
            smask[r * 8 + q * 2 + g] = m;
            cnt += __popc(m);
        }
        scnt[r * 4 + q] = cnt;
    }

    // ---- per-thread constants ---------------------------------------------------
    const int arow = lane >> 2;                 // 0..7 (mma row group / epilogue)

    // convert mapping: r = tid&127 (row), q = tid>>7 (k-quarter)
    const int cr = tid & 127;
    const int cq = tid >> 7;
    const uint32_t crx = (uint32_t)(cr & 7) << 4;
    const uint32_t csrc_off = (uint32_t)(cq >> 1) * 16384 + (uint32_t)cr * 128;
    const uint32_t cu0 = (uint32_t)(cq & 1) * 4;
    const uint32_t cdst_row = (uint32_t)cr * 128;

    // ldmatrix lane addressing
    const uint32_t l7 = lane & 7;
    const uint32_t lxor = l7 << 4;              // SW128 XOR field (row&7)
    // A: lanes 0-7: (m lo, k lo) 8-15: (m hi, k lo) 16-23: (m lo, k hi) 24-31: (m hi, k hi)
    const uint32_t a_row = (uint32_t)(wm * 32) + l7 + ((lane >> 3) & 1) * 8;
    const uint32_t a_kseg = ((lane >> 4) & 1) * 16;
    const uint32_t a_base_off = a_row * 128;    // + mf*16*128
    // B: lanes 0-7: (n lo, k lo) 8-15: (n lo, k hi) 16-23: (n hi, k lo) 24-31: (n hi, k hi)
    const uint32_t b_row = (uint32_t)(wn * 64) + l7 + ((lane >> 4) & 1) * 8;
    const uint32_t b_kseg = ((lane >> 3) & 1) * 16;
    const uint32_t b_base_off = b_row * 128;    // + np*16*128

    float c[2][8][4];
    #pragma unroll
    for (int mf = 0; mf < 2; mf++)
        #pragma unroll
        for (int nf = 0; nf < 8; nf++)
            #pragma unroll
            for (int e = 0; e < 4; e++) c[mf][nf][e] = 0.0f;

    // ---- prologue convert: chunk 0 -> A16 buf 0 --------------------------------
    MBARRIER_WAIT_PARITY(sb + MBAR_A(0), 0);
    {
        const uint32_t src = sb + A32_OFF(0) + csrc_off;
        const uint32_t dst = sb + A16_OFF + cdst_row;
        float4 f0 = lds128f(src + (((cu0 + 0) << 4) ^ crx));
        float4 f1 = lds128f(src + (((cu0 + 1) << 4) ^ crx));
        float4 f2 = lds128f(src + (((cu0 + 2) << 4) ^ crx));
        float4 f3 = lds128f(src + (((cu0 + 3) << 4) ^ crx));
        sts128(dst + (((uint32_t)(cq * 2 + 0) << 4) ^ crx),
               packh2(f0.x, f0.y), packh2(f0.z, f0.w),
               packh2(f1.x, f1.y), packh2(f1.z, f1.w));
        sts128(dst + (((uint32_t)(cq * 2 + 1) << 4) ^ crx),
               packh2(f2.x, f2.y), packh2(f2.z, f2.w),
               packh2(f3.x, f3.y), packh2(f3.z, f3.w));
    }
    __syncthreads();

    // ---- mainloop: 8 x BK=64, one sync per iter ---------------------------------
    #pragma unroll
    for (int i = 0; i < NITER; i++) {
        // (1) convert chunk i+1 into the other A16 buffer (overlaps MMA issue)
        if (i + 1 < NITER) {
            const int j = i + 1;
            MBARRIER_WAIT_PARITY(sb + MBAR_A(j % 3), (j / 3) & 1);
            const uint32_t src = sb + A32_OFF(j % 3) + csrc_off;
            const uint32_t dst = sb + A16_OFF + (uint32_t)(j & 1) * 16384 + cdst_row;
            float4 f0 = lds128f(src + (((cu0 + 0) << 4) ^ crx));
            float4 f1 = lds128f(src + (((cu0 + 1) << 4) ^ crx));
            float4 f2 = lds128f(src + (((cu0 + 2) << 4) ^ crx));
            float4 f3 = lds128f(src + (((cu0 + 3) << 4) ^ crx));
            sts128(dst + (((uint32_t)(cq * 2 + 0) << 4) ^ crx),
                   packh2(f0.x, f0.y), packh2(f0.z, f0.w),
                   packh2(f1.x, f1.y), packh2(f1.z, f1.w));
            sts128(dst + (((uint32_t)(cq * 2 + 1) << 4) ^ crx),
                   packh2(f2.x, f2.y), packh2(f2.z, f2.w),
                   packh2(f3.x, f3.y), packh2(f3.z, f3.w));
        }

        // (2) MMAs on A16 buf i&1 + B slot i%2
        MBARRIER_WAIT_PARITY(sb + MBAR_B(i & 1), (i / 2) & 1);
        {
            const uint32_t aB = sb + A16_OFF + (uint32_t)(i & 1) * 16384 + a_base_off;
            const uint32_t bB = sb + B_OFF(i & 1) + b_base_off;
            #pragma unroll
            for (int ks = 0; ks < 4; ks++) {
                const uint32_t ak = ((uint32_t)ks * 32 + a_kseg) ^ lxor;
                const uint32_t bk = ((uint32_t)ks * 32 + b_kseg) ^ lxor;
                uint32_t ra[2][4];
                ldsm_x4(ra[0], aB + ak);             // m rows wm*32 + 0..15
                ldsm_x4(ra[1], aB + 2048 + ak);      // + 16*128 bytes
                #pragma unroll
                for (int np = 0; np < 4; np++) {
                    uint32_t rb[4];
                    ldsm_x4(rb, bB + (uint32_t)np * 2048 + bk);
                    mma16816(c[0][np * 2 + 0], ra[0], rb);
                    mma16816(c[0][np * 2 + 1], ra[0], rb + 2);
                    mma16816(c[1][np * 2 + 0], ra[1], rb);
                    mma16816(c[1][np * 2 + 1], ra[1], rb + 2);
                }
            }
        }
        __syncthreads();

        // (3) refills (slots just freed by the sync)
        if (tid == 0) {
            if (i + 3 < NITER) {
                const int j = i + 3;
                MBARRIER_EXPECT_TX(sb + MBAR_A(j % 3), TXA);
                TMA_LOAD_2D(sb + A32_OFF(j % 3),         &tmap_a, j * BK,      tile, sb + MBAR_A(j % 3));
                TMA_LOAD_2D(sb + A32_OFF(j % 3) + 16384, &tmap_a, j * BK + 32, tile, sb + MBAR_A(j % 3));
            }
            if (i + 2 < NITER) {
                const int j = i + 2;
                MBARRIER_EXPECT_TX(sb + MBAR_B(j & 1), TXB);
                TMA_LOAD_2D(sb + B_OFF(j & 1), &tmap_b, j * BK, 0, sb + MBAR_B(j & 1));
            }
        }
    }

    // ---- epilogue: scale by 1/cnt on mask, elu, store ---------------------------
    #pragma unroll
    for (int mf = 0; mf < 2; mf++) {
        const int r0 = wm * 32 + mf * 16 + arow;
        #pragma unroll
        for (int half = 0; half < 2; half++) {
            const int rr = r0 + half * 8;
            const int grow = tile + rr;
            const bool valid = (grow < N_ROWS);
            const int cnt = scnt[rr * 4] + scnt[rr * 4 + 1] +
                            scnt[rr * 4 + 2] + scnt[rr * 4 + 3];
            const bool all_on = (cnt == 0);
            const float scale = all_on ? (1.0f / 256.0f) : (1.0f / (float)cnt);
            #pragma unroll
            for (int nf = 0; nf < 8; nf++) {
                const int col = wn * 64 + nf * 8 + (int)(lane & 3) * 2;
                const uint32_t mw = smask[rr * 8 + (col >> 5)];
                float2 o;
                #pragma unroll
                for (int e = 0; e < 2; e++) {
                    float h = c[mf][nf][half * 2 + e];
                    bool on = all_on | (((mw >> ((col + e) & 31)) & 1u) != 0u);
                    float v = on ? h * scale : 0.0f;
                    float res = (v > 0.0f) ? v : (__expf(v) - 1.0f);
                    ((float*)&o)[e] = res;
                }
                if (valid)
                    *(float2*)(out + (size_t)grow * M_DIM + col) = o;
            }
        }
    }
}

// ============================================================================
// host launch
// ============================================================================
typedef CUresult (*EncodeTiledFn)(
    CUtensorMap*, CUtensorMapDataType, cuuint32_t, void*,
    const cuuint64_t*, const cuuint64_t*, const cuuint32_t*, const cuuint32_t*,
    CUtensorMapInterleave, CUtensorMapSwizzle, CUtensorMapL2promotion,
    CUtensorMapFloatOOBfill);

extern "C" void kernel_launch(void* const* d_in, const int* in_sizes, int n_in,
                              void* d_out, int out_size) {
    const float* inp = (const float*)d_in[0];
    const int*   adj = (const int*)d_in[1];
    const float* W   = (const float*)d_in[2];
    // d_in[3] ('a') provably cancels in the softmax; unused.
    float* out = (float*)d_out;

    prep_wh_kernel<<<(K_DIM * M_DIM) / 256, 256>>>(W);

    void* wh_ptr = nullptr;
    cudaGetSymbolAddress(&wh_ptr, g_Wh);

    void* fp = nullptr;
    cudaDriverEntryPointQueryResult qres;
    cudaGetDriverEntryPointByVersion("cuTensorMapEncodeTiled", &fp, 12000,
                                     cudaEnableDefault, &qres);
    EncodeTiledFn enc = (EncodeTiledFn)fp;

    alignas(64) CUtensorMap tmA;
    alignas(64) CUtensorMap tmB;
    {
        cuuint64_t dims[2]    = {(cuuint64_t)K_DIM, (cuuint64_t)N_ROWS};
        cuuint64_t strides[1] = {(cuuint64_t)K_DIM * sizeof(float)};
        cuuint32_t box[2]     = {32u, (cuuint32_t)BM};      // 128B x 128 rows
        cuuint32_t es[2]      = {1, 1};
        enc(&tmA, CU_TENSOR_MAP_DATA_TYPE_FLOAT32, 2, (void*)inp,
            dims, strides, box, es,
            CU_TENSOR_MAP_INTERLEAVE_NONE, CU_TENSOR_MAP_SWIZZLE_128B,
            CU_TENSOR_MAP_L2_PROMOTION_L2_128B, CU_TENSOR_MAP_FLOAT_OOB_FILL_NONE);
    }
    {
        cuuint64_t dims[2]    = {(cuuint64_t)K_DIM, (cuuint64_t)M_DIM};
        cuuint64_t strides[1] = {(cuuint64_t)K_DIM * sizeof(__half)};
        cuuint32_t box[2]     = {64u, (cuuint32_t)M_DIM};   // 128B x 256 rows
        cuuint32_t es[2]      = {1, 1};
        enc(&tmB, CU_TENSOR_MAP_DATA_TYPE_FLOAT16, 2, wh_ptr,
            dims, strides, box, es,
            CU_TENSOR_MAP_INTERLEAVE_NONE, CU_TENSOR_MAP_SWIZZLE_128B,
            CU_TENSOR_MAP_L2_PROMOTION_L2_128B, CU_TENSOR_MAP_FLOAT_OOB_FILL_NONE);
    }

    static bool attr_set = false;
    if (!attr_set) {
        cudaFuncSetAttribute(gat_kernel,
                             cudaFuncAttributeMaxDynamicSharedMemorySize,
                             SMEM_TOTAL);
        attr_set = true;
    }
    const int grid = (N_ROWS + BM - 1) / BM;   // 1563
    gat_kernel<<<grid, THREADS, SMEM_TOTAL>>>(tmA, tmB, adj, out);
}

// round 7
// speedup vs baseline: 1.5304x; 1.1984x over previous
#include <cuda.h>
#include <cuda_runtime.h>
#include <cuda_fp16.h>
#include <cstdint>

// ============================================================================
// out = elu( (adj>0 ? (input@W)/cnt_row : 0) ), cnt_row = #(adj>0 in row);
// cnt==0 rows: softmax of all-(-9e15) is uniform 1/256.
// R7: R6 was barrier/dependency-exposure bound with 1 CTA/SM (issue 16%,
//     nothing saturated). Shrink CTA to BM=64/256 threads/108KB smem/<=128
//     regs so TWO CTAs co-reside per SM — cross-CTA interleaving hides the
//     per-iteration sync + scoreboard shadows. 64 | 200000 -> no bounds checks.
// ============================================================================

#define N_ROWS 200000
#define K_DIM  512
#define M_DIM  256
#define BM     64
#define BK     64
#define NITER  (K_DIM / BK)     // 8
#define THREADS 256             // 8 warps: 2 (m) x 4 (n), warp tile 32x64

// --- shared memory layout (bytes) --------------------------------------------
// mbars @0 (A:0,8  B:16,24), MASK @128 (u32[64][8] -> 2176), CNT @2176
// (int[64][4] -> 3200), A16 @3584 (8KB, fp16 [64][64], ends 11776),
// A32 @12288 (2 x 16KB; each = two 8KB subtiles of fp32 [64][32] SW128),
// B @45056 (2 x 32KB, fp16 [256][64] SW128). Total 110592 (108KB) -> 2 CTAs/SM.
#define MBAR_A(s)  ((s) * 8)
#define MBAR_B(s)  (16 + (s) * 8)
#define MASK_OFF   128
#define CNT_OFF    (MASK_OFF + 64 * 8 * 4)      // 2176
#define A16_OFF    3584
#define A32_OFF(s) (12288 + (s) * 16384)
#define B_OFF(s)   (45056 + (s) * 32768)
#define SMEM_TOTAL 110592
#define TXA        16384
#define TXB        32768

// --- device scratch: W transposed to [M][K], fp16 RN --------------------------
__device__ __half g_Wh[M_DIM * K_DIM];

// ============================================================================
// helpers (plain sm_90-level PTX; no 'a' features)
// ============================================================================
__device__ __forceinline__ uint32_t smem_u32(const void* p) {
    uint32_t a;
    asm("{ .reg .u64 t; cvta.to.shared.u64 t, %1; cvt.u32.u64 %0, t; }"
        : "=r"(a) : "l"(p));
    return a;
}
#define MBARRIER_INIT(mbar, count) \
    asm volatile("mbarrier.init.shared.b64 [%0], %1;" \
        :: "r"((uint32_t)(mbar)), "r"((uint32_t)(count)) : "memory")
#define MBARRIER_EXPECT_TX(mbar, bytes) \
    asm volatile("mbarrier.arrive.expect_tx.shared.b64 _, [%0], %1;" \
        :: "r"((uint32_t)(mbar)), "r"((uint32_t)(bytes)) : "memory")
#define MBARRIER_WAIT_PARITY(mbar, parity) do { \
    uint32_t _mbar = (uint32_t)(mbar); \
    uint32_t _par = (uint32_t)(parity); \
    uint32_t _done; \
    asm volatile( \
        "{\n\t.reg .pred p;\n\t" \
        "mbarrier.try_wait.parity.acquire.cta.shared::cta.b64 p, [%1], %2;\n\t" \
        "selp.b32 %0, 1, 0, p;\n\t}" \
        : "=r"(_done) : "r"(_mbar), "r"(_par) : "memory"); \
    if (!_done) { \
        asm volatile( \
            "{\n\t.reg .pred P1;\n\t" \
            "WAIT_LOOP_%=:\n\t" \
            "mbarrier.try_wait.parity.acquire.cta.shared::cta.b64 P1, [%0], %1, 0x989680;\n\t" \
            "@P1 bra.uni WAIT_DONE_%=;\n\t" \
            "bra.uni WAIT_LOOP_%=;\n\t" \
            "WAIT_DONE_%=:\n\t}" \
            :: "r"(_mbar), "r"(_par) : "memory"); \
    } \
} while (0)
#define TMA_LOAD_2D(smem_addr, map_ptr, cx, cy, mbar) \
    asm volatile( \
        "cp.async.bulk.tensor.2d.shared::cta.global.tile.mbarrier::complete_tx::bytes " \
        "[%0], [%1, {%2, %3}], [%4];" \
        :: "r"((uint32_t)(smem_addr)), "l"(map_ptr), \
           "r"((int32_t)(cx)), "r"((int32_t)(cy)), "r"((uint32_t)(mbar)) \
        : "memory")

__device__ __forceinline__ float4 lds128f(uint32_t a) {
    float4 v;
    asm volatile("ld.shared.v4.f32 {%0,%1,%2,%3}, [%4];"
                 : "=f"(v.x), "=f"(v.y), "=f"(v.z), "=f"(v.w) : "r"(a));
    return v;
}
__device__ __forceinline__ void sts128(uint32_t a, uint32_t r0, uint32_t r1,
                                       uint32_t r2, uint32_t r3) {
    asm volatile("st.shared.v4.b32 [%0], {%1,%2,%3,%4};"
                 :: "r"(a), "r"(r0), "r"(r1), "r"(r2), "r"(r3) : "memory");
}
__device__ __forceinline__ void ldsm_x4(uint32_t* r, uint32_t addr) {
    asm volatile("ldmatrix.sync.aligned.m8n8.x4.shared.b16 {%0,%1,%2,%3}, [%4];"
                 : "=r"(r[0]), "=r"(r[1]), "=r"(r[2]), "=r"(r[3]) : "r"(addr));
}
__device__ __forceinline__ uint32_t packh2(float lo, float hi) {
    uint32_t d;
    asm("cvt.rn.f16x2.f32 %0, %1, %2;" : "=r"(d) : "f"(hi), "f"(lo));
    return d;
}
__device__ __forceinline__ void mma16816(float* c, const uint32_t* a,
                                         const uint32_t* b) {
    asm volatile(
        "mma.sync.aligned.m16n8k16.row.col.f32.f16.f16.f32 "
        "{%0,%1,%2,%3}, {%4,%5,%6,%7}, {%8,%9}, {%0,%1,%2,%3};"
        : "+f"(c[0]), "+f"(c[1]), "+f"(c[2]), "+f"(c[3])
        : "r"(a[0]), "r"(a[1]), "r"(a[2]), "r"(a[3]), "r"(b[0]), "r"(b[1]));
}

// ============================================================================
// prep: W [K=512, M=256] row-major fp32 -> g_Wh [M][K] fp16 (RN)
// ============================================================================
__global__ void prep_wh_kernel(const float* __restrict__ W) {
    int idx = blockIdx.x * blockDim.x + threadIdx.x;
    int k = idx >> 8;
    int m = idx & 255;
    g_Wh[m * K_DIM + k] = __float2half_rn(W[idx]);
}

// ============================================================================
// fused GEMM (TMA + smem-convert + ldmatrix + mma.sync) + attention + elu
// ============================================================================
__global__ void __launch_bounds__(THREADS, 2) gat_kernel(
    const __grid_constant__ CUtensorMap tmap_a,
    const __grid_constant__ CUtensorMap tmap_b,
    const int* __restrict__ adj,
    float* __restrict__ out)
{
    extern __shared__ char smem[];
    const uint32_t sb = smem_u32(smem);
    uint32_t* smask = (uint32_t*)(smem + MASK_OFF);   // [64][8]
    int* scnt = (int*)(smem + CNT_OFF);               // [64][4]

    const int tid  = threadIdx.x;
    const int lane = tid & 31;
    const int wid  = tid >> 5;
    const int wm   = wid >> 2;   // 0..1 : 32-row band
    const int wn   = wid & 3;    // 0..3 : 64-col band
    const int tile = blockIdx.x * BM;

    // ---- mbarrier init + TMA prologue -----------------------------------------
    if (tid == 0) {
        MBARRIER_INIT(sb + MBAR_A(0), 1);
        MBARRIER_INIT(sb + MBAR_A(1), 1);
        MBARRIER_INIT(sb + MBAR_B(0), 1);
        MBARRIER_INIT(sb + MBAR_B(1), 1);
    }
    __syncthreads();
    if (tid == 0) {
        #pragma unroll
        for (int j = 0; j < 2; j++) {
            MBARRIER_EXPECT_TX(sb + MBAR_A(j), TXA);
            TMA_LOAD_2D(sb + A32_OFF(j),        &tmap_a, j * BK,      tile, sb + MBAR_A(j));
            TMA_LOAD_2D(sb + A32_OFF(j) + 8192, &tmap_a, j * BK + 32, tile, sb + MBAR_A(j));
            MBARRIER_EXPECT_TX(sb + MBAR_B(j), TXB);
            TMA_LOAD_2D(sb + B_OFF(j), &tmap_b, j * BK, 0, sb + MBAR_B(j));
        }
    }

    // ---- adj mask + count (overlaps TMA flight; 64 | N_ROWS, no clamps) --------
    {
        int r = tid >> 2;            // 0..63
        int q = tid & 3;             // 64-col quarter
        const int4* ap = (const int4*)(adj + (size_t)(tile + r) * M_DIM + q * 64);
        int cnt = 0;
        #pragma unroll
        for (int g = 0; g < 2; g++) {
            uint32_t m = 0;
            #pragma unroll
            for (int w = 0; w < 8; w++) {
                int4 v = __ldg(ap + g * 8 + w);
                m |= (v.x > 0 ? 1u : 0u) << (w * 4 + 0);
                m |= (v.y > 0 ? 1u : 0u) << (w * 4 + 1);
                m |= (v.z > 0 ? 1u : 0u) << (w * 4 + 2);
                m |= (v.w > 0 ? 1u : 0u) << (w * 4 + 3);
            }
            smask[r * 8 + q * 2 + g] = m;
            cnt += __popc(m);
        }
        scnt[r * 4 + q] = cnt;
    }

    // ---- per-thread constants ----------------------------------------------------
    const int arow = lane >> 2;                 // 0..7

    // convert mapping: row cr = tid>>2 (0..63), k-quarter cq = tid&3
    const int cr = tid >> 2;
    const int cq = tid & 3;
    const uint32_t crx = (uint32_t)(cr & 7) << 4;
    const uint32_t csrc_off = (uint32_t)(cq >> 1) * 8192 + (uint32_t)cr * 128;
    const uint32_t cu0 = (uint32_t)(cq & 1) * 4;
    const uint32_t cdst = sb + A16_OFF + (uint32_t)cr * 128;

    // ldmatrix lane addressing (SW128 XOR on 128B rows)
    const uint32_t l7 = lane & 7;
    const uint32_t lxor = l7 << 4;
    const uint32_t a_row = (uint32_t)(wm * 32) + l7 + ((lane >> 3) & 1) * 8;
    const uint32_t a_kseg = ((lane >> 4) & 1) * 16;
    const uint32_t a_base = sb + A16_OFF + a_row * 128;
    const uint32_t b_row = (uint32_t)(wn * 64) + l7 + ((lane >> 4) & 1) * 8;
    const uint32_t b_kseg = ((lane >> 3) & 1) * 16;
    const uint32_t b_base_off = b_row * 128;

    float c[2][8][4];
    #pragma unroll
    for (int mf = 0; mf < 2; mf++)
        #pragma unroll
        for (int nf = 0; nf < 8; nf++)
            #pragma unroll
            for (int e = 0; e < 4; e++) c[mf][nf][e] = 0.0f;

    // ---- mainloop: 8 x BK=64 -------------------------------------------------------
    #pragma unroll 1
    for (int i = 0; i < NITER; i++) {
        const int s = i & 1;
        const uint32_t ph = (uint32_t)((i >> 1) & 1);

        // (1) convert A32[s] -> A16 (fp16, SW128-XOR layout), conflict-free
        MBARRIER_WAIT_PARITY(sb + MBAR_A(s), ph);
        {
            const uint32_t src = sb + A32_OFF(s) + csrc_off;
            float4 f0 = lds128f(src + (((cu0 + 0) << 4) ^ crx));
            float4 f1 = lds128f(src + (((cu0 + 1) << 4) ^ crx));
            float4 f2 = lds128f(src + (((cu0 + 2) << 4) ^ crx));
            float4 f3 = lds128f(src + (((cu0 + 3) << 4) ^ crx));
            sts128(cdst + (((uint32_t)(cq * 2 + 0) << 4) ^ crx),
                   packh2(f0.x, f0.y), packh2(f0.z, f0.w),
                   packh2(f1.x, f1.y), packh2(f1.z, f1.w));
            sts128(cdst + (((uint32_t)(cq * 2 + 1) << 4) ^ crx),
                   packh2(f2.x, f2.y), packh2(f2.z, f2.w),
                   packh2(f3.x, f3.y), packh2(f3.z, f3.w));
        }
        __syncthreads();

        // (2) MMAs on A16 + B slot s
        MBARRIER_WAIT_PARITY(sb + MBAR_B(s), ph);
        {
            const uint32_t bB = sb + B_OFF(s) + b_base_off;
            #pragma unroll
            for (int ks = 0; ks < 4; ks++) {
                const uint32_t ak = ((uint32_t)ks * 32 + a_kseg) ^ lxor;
                const uint32_t bk = ((uint32_t)ks * 32 + b_kseg) ^ lxor;
                uint32_t ra[2][4];
                ldsm_x4(ra[0], a_base + ak);
                ldsm_x4(ra[1], a_base + 2048 + ak);
                #pragma unroll
                for (int np = 0; np < 4; np++) {
                    uint32_t rb[4];
                    ldsm_x4(rb, bB + (uint32_t)np * 2048 + bk);
                    mma16816(c[0][np * 2 + 0], ra[0], rb);
                    mma16816(c[0][np * 2 + 1], ra[0], rb + 2);
                    mma16816(c[1][np * 2 + 0], ra[1], rb);
                    mma16816(c[1][np * 2 + 1], ra[1], rb + 2);
                }
            }
        }
        __syncthreads();

        // (3) refill slot s for iteration i+2
        if (i + 2 < NITER && tid == 0) {
            const int j = i + 2;
            MBARRIER_EXPECT_TX(sb + MBAR_A(s), TXA);
            TMA_LOAD_2D(sb + A32_OFF(s),        &tmap_a, j * BK,      tile, sb + MBAR_A(s));
            TMA_LOAD_2D(sb + A32_OFF(s) + 8192, &tmap_a, j * BK + 32, tile, sb + MBAR_A(s));
            MBARRIER_EXPECT_TX(sb + MBAR_B(s), TXB);
            TMA_LOAD_2D(sb + B_OFF(s), &tmap_b, j * BK, 0, sb + MBAR_B(s));
        }
    }

    // ---- epilogue: scale by 1/cnt on mask, elu, store -------------------------------
    #pragma unroll
    for (int mf = 0; mf < 2; mf++) {
        const int r0 = wm * 32 + mf * 16 + arow;
        #pragma unroll
        for (int half = 0; half < 2; half++) {
            const int rr = r0 + half * 8;
            const int grow = tile + rr;
            const int cnt = scnt[rr * 4] + scnt[rr * 4 + 1] +
                            scnt[rr * 4 + 2] + scnt[rr * 4 + 3];
            const bool all_on = (cnt == 0);
            const float scale = all_on ? (1.0f / 256.0f) : (1.0f / (float)cnt);
            #pragma unroll
            for (int nf = 0; nf < 8; nf++) {
                const int col = wn * 64 + nf * 8 + (int)(lane & 3) * 2;
                const uint32_t mw = smask[rr * 8 + (col >> 5)];
                float2 o;
                #pragma unroll
                for (int e = 0; e < 2; e++) {
                    float h = c[mf][nf][half * 2 + e];
                    bool on = all_on | (((mw >> ((col + e) & 31)) & 1u) != 0u);
                    float v = on ? h * scale : 0.0f;
                    float res = (v > 0.0f) ? v : (__expf(v) - 1.0f);
                    ((float*)&o)[e] = res;
                }
                *(float2*)(out + (size_t)grow * M_DIM + col) = o;
            }
        }
    }
}

// ============================================================================
// host launch
// ============================================================================
typedef CUresult (*EncodeTiledFn)(
    CUtensorMap*, CUtensorMapDataType, cuuint32_t, void*,
    const cuuint64_t*, const cuuint64_t*, const cuuint32_t*, const cuuint32_t*,
    CUtensorMapInterleave, CUtensorMapSwizzle, CUtensorMapL2promotion,
    CUtensorMapFloatOOBfill);

extern "C" void kernel_launch(void* const* d_in, const int* in_sizes, int n_in,
                              void* d_out, int out_size) {
    const float* inp = (const float*)d_in[0];
    const int*   adj = (const int*)d_in[1];
    const float* W   = (const float*)d_in[2];
    // d_in[3] ('a') provably cancels in the softmax; unused.
    float* out = (float*)d_out;

    prep_wh_kernel<<<(K_DIM * M_DIM) / 256, 256>>>(W);

    void* wh_ptr = nullptr;
    cudaGetSymbolAddress(&wh_ptr, g_Wh);

    void* fp = nullptr;
    cudaDriverEntryPointQueryResult qres;
    cudaGetDriverEntryPointByVersion("cuTensorMapEncodeTiled", &fp, 12000,
                                     cudaEnableDefault, &qres);
    EncodeTiledFn enc = (EncodeTiledFn)fp;

    alignas(64) CUtensorMap tmA;
    alignas(64) CUtensorMap tmB;
    {
        cuuint64_t dims[2]    = {(cuuint64_t)K_DIM, (cuuint64_t)N_ROWS};
        cuuint64_t strides[1] = {(cuuint64_t)K_DIM * sizeof(float)};
        cuuint32_t box[2]     = {32u, (cuuint32_t)BM};      // 128B x 64 rows
        cuuint32_t es[2]      = {1, 1};
        enc(&tmA, CU_TENSOR_MAP_DATA_TYPE_FLOAT32, 2, (void*)inp,
            dims, strides, box, es,
            CU_TENSOR_MAP_INTERLEAVE_NONE, CU_TENSOR_MAP_SWIZZLE_128B,
            CU_TENSOR_MAP_L2_PROMOTION_L2_128B, CU_TENSOR_MAP_FLOAT_OOB_FILL_NONE);
    }
    {
        cuuint64_t dims[2]    = {(cuuint64_t)K_DIM, (cuuint64_t)M_DIM};
        cuuint64_t strides[1] = {(cuuint64_t)K_DIM * sizeof(__half)};
        cuuint32_t box[2]     = {64u, (cuuint32_t)M_DIM};   // 128B x 256 rows
        cuuint32_t es[2]      = {1, 1};
        enc(&tmB, CU_TENSOR_MAP_DATA_TYPE_FLOAT16, 2, wh_ptr,
            dims, strides, box, es,
            CU_TENSOR_MAP_INTERLEAVE_NONE, CU_TENSOR_MAP_SWIZZLE_128B,
            CU_TENSOR_MAP_L2_PROMOTION_L2_128B, CU_TENSOR_MAP_FLOAT_OOB_FILL_NONE);
    }

    static bool attr_set = false;
    if (!attr_set) {
        cudaFuncSetAttribute(gat_kernel,
                             cudaFuncAttributeMaxDynamicSharedMemorySize,
                             SMEM_TOTAL);
        attr_set = true;
    }
    const int grid = N_ROWS / BM;   // 3125 (exact)
    gat_kernel<<<grid, THREADS, SMEM_TOTAL>>>(tmA, tmB, adj, out);
}